// round 7
// baseline (speedup 1.0000x reference)
#include <cuda_runtime.h>
#include <cuda_bf16.h>
#include <cstddef>

// Problem constants
#define SS   48      // sequence length
#define NBLK 128     // persistent grid size (<= 148 SMs -> all co-resident)
#define EPSL 1e-5f

// ---------------- device scratch (allocation-free rule: __device__ globals) ---
__device__ float g_g0[2 * SS * 64 * 2048];   // LN(x @ W_ih0^T): row = d*3072+s*64+b
__device__ float g_g1[2 * 64 * 2048];        // LN(xc @ W_ih1^T): row = d*64+b
__device__ float g_pre[2 * 64 * 2048];       // per-step h @ W_hh^T
__device__ float g_h[2 * 64 * 512];          // hidden state [d][b][k]
__device__ float g_xc[64 * 1024];            // concat(hf, hb) [b][1024]
__device__ unsigned g_cnt;                   // grid-barrier arrival counter

// ---------------- helpers ----------------
__device__ __forceinline__ float sigf(float x) { return 1.f / (1.f + __expf(-x)); }

// block-wide (256 threads, 8 warps) sum; returns total to all threads
__device__ __forceinline__ float blk_sum(float x, float* sred) {
#pragma unroll
    for (int o = 16; o > 0; o >>= 1) x += __shfl_down_sync(0xffffffffu, x, o);
    const int w = threadIdx.x >> 5;
    if ((threadIdx.x & 31) == 0) sred[w] = x;
    __syncthreads();
    float t = 0.f;
#pragma unroll
    for (int i = 0; i < 8; ++i) t += sred[i];
    __syncthreads();
    return t;
}

// grid-wide barrier over exactly NBLK resident CTAs.
// Monotonic counter (zeroed by k_init before each persistent launch); barrier t
// waits for g_cnt >= NBLK*t. Race-free without any synchronized start.
__device__ __forceinline__ void gbar(int* nbar) {
    __syncthreads();
    if (threadIdx.x == 0) {
        ++(*nbar);
        const unsigned tgt = (unsigned)(*nbar) * NBLK;
        __threadfence();
        atomicAdd(&g_cnt, 1u);
        while (*(volatile unsigned*)&g_cnt < tgt) __nanosleep(64);
        __threadfence();
    }
    __syncthreads();
}

// ---------------- K0: init hidden state + barrier counter ----------------
__global__ void k_init() {
    const int i = blockIdx.x * 256 + threadIdx.x;
    if (i < 2 * 64 * 512) g_h[i] = 0.f;
    if (i == 0) g_cnt = 0u;
}

// ---------------- K1: input GEMM  g0raw[row][g] = x[b][s][:] . w_ih0[d][g][:]
// row = d*3072 + s*64 + b.  M=6144, N=2048, K=512. 128x128 tiles, 8x8 micro.
__global__ __launch_bounds__(256) void k_gemm_ih0(const float* __restrict__ x,
                                                  const float* __restrict__ w) {
    __shared__ float Asm[16 * 132];   // [k][m]
    __shared__ float Wsm[16 * 132];   // [k][n]
    const int tid   = threadIdx.x;
    const int tcol  = tid & 15;
    const int trow  = tid >> 4;
    const int mbase = blockIdx.y * 128;
    const int nbase = blockIdx.x * 128;
    const int d     = mbase / 3072;   // tile never straddles a direction

    float acc[8][8];
#pragma unroll
    for (int i = 0; i < 8; ++i)
#pragma unroll
        for (int j = 0; j < 8; ++j) acc[i][j] = 0.f;

    for (int k0 = 0; k0 < 512; k0 += 16) {
        __syncthreads();
        // stage A tile (2048 floats) and W tile (2048 floats)
#pragma unroll
        for (int it = 0; it < 2; ++it) {
            const int idx = tid + 256 * it;
            const int m   = idx >> 2;
            const int kq  = (idx & 3) * 4;
            const int rem = (mbase + m) % 3072;
            const int s   = rem >> 6;
            const int b   = rem & 63;
            float4 va = *(const float4*)(x + ((size_t)(b * 48 + s)) * 512 + k0 + kq);
            Asm[(kq + 0) * 132 + m] = va.x;
            Asm[(kq + 1) * 132 + m] = va.y;
            Asm[(kq + 2) * 132 + m] = va.z;
            Asm[(kq + 3) * 132 + m] = va.w;
            float4 vw = *(const float4*)(w + ((size_t)(d * 2048 + nbase + m)) * 512 + k0 + kq);
            Wsm[(kq + 0) * 132 + m] = vw.x;
            Wsm[(kq + 1) * 132 + m] = vw.y;
            Wsm[(kq + 2) * 132 + m] = vw.z;
            Wsm[(kq + 3) * 132 + m] = vw.w;
        }
        __syncthreads();
#pragma unroll
        for (int kk = 0; kk < 16; ++kk) {
            float4 a0 = *(const float4*)&Asm[kk * 132 + trow * 4];
            float4 a1 = *(const float4*)&Asm[kk * 132 + 64 + trow * 4];
            float4 b0 = *(const float4*)&Wsm[kk * 132 + tcol * 4];
            float4 b1 = *(const float4*)&Wsm[kk * 132 + 64 + tcol * 4];
            const float av[8] = {a0.x, a0.y, a0.z, a0.w, a1.x, a1.y, a1.z, a1.w};
            const float bv[8] = {b0.x, b0.y, b0.z, b0.w, b1.x, b1.y, b1.z, b1.w};
#pragma unroll
            for (int i = 0; i < 8; ++i)
#pragma unroll
                for (int j = 0; j < 8; ++j) acc[i][j] = fmaf(av[i], bv[j], acc[i][j]);
        }
    }
    // epilogue
#pragma unroll
    for (int i = 0; i < 8; ++i) {
        const int m = (i < 4) ? (trow * 4 + i) : (64 + trow * 4 + (i - 4));
        const size_t ro = (size_t)(mbase + m) * 2048 + nbase;
        float4 o0 = make_float4(acc[i][0], acc[i][1], acc[i][2], acc[i][3]);
        float4 o1 = make_float4(acc[i][4], acc[i][5], acc[i][6], acc[i][7]);
        *(float4*)(g_g0 + ro + tcol * 4)      = o0;
        *(float4*)(g_g0 + ro + 64 + tcol * 4) = o1;
    }
}

// ---------------- K2: in-place row LayerNorm over width 2048 -----------------
// which: 0 -> g_g0, 1 -> g_g1. d = row / rows_per_dir selects gamma/beta slice.
__global__ __launch_bounds__(256) void k_ln_rows(int which,
                                                 const float* __restrict__ gam,
                                                 const float* __restrict__ bet,
                                                 int rows_per_dir) {
    __shared__ float sred[8];
    float* p = which ? g_g1 : g_g0;
    const int row = blockIdx.x;
    const int d   = row / rows_per_dir;
    const size_t base = (size_t)row * 2048;
    float v[8];
#pragma unroll
    for (int r = 0; r < 8; ++r) v[r] = p[base + threadIdx.x + 256 * r];
    float s = 0.f;
#pragma unroll
    for (int r = 0; r < 8; ++r) s += v[r];
    const float mu = blk_sum(s, sred) * (1.f / 2048.f);
    float sq = 0.f;
#pragma unroll
    for (int r = 0; r < 8; ++r) { const float t = v[r] - mu; sq += t * t; }
    const float var = blk_sum(sq, sred) * (1.f / 2048.f);
    const float rs  = rsqrtf(var + EPSL);
#pragma unroll
    for (int r = 0; r < 8; ++r) {
        const int idx = threadIdx.x + 256 * r;
        p[base + idx] = (v[r] - mu) * rs * gam[d * 2048 + idx] + bet[d * 2048 + idx];
    }
}

// ---------------- K3: xc GEMM  g1raw[d][b][g] = xc[b][:1024] . w_ih1[d][g][:]
// CTA j: d=j&1, 32-g slice (j>>1); all 64 batches. K=1024.
__global__ __launch_bounds__(256) void k_gemm_xc(const float* __restrict__ w) {
    __shared__ float As[64 * 68];
    __shared__ float Ws[32 * 68];
    const int tid = threadIdx.x;
    const int j   = blockIdx.x;
    const int d   = j & 1;
    const int gB  = (j >> 1) * 32;
    const int tx  = tid & 31, ty = tid >> 5;
    float acc[8] = {0.f, 0.f, 0.f, 0.f, 0.f, 0.f, 0.f, 0.f};
    const float* wbase = w + ((size_t)(d * 2048 + gB)) * 1024;
    for (int k0 = 0; k0 < 1024; k0 += 64) {
        __syncthreads();
#pragma unroll
        for (int it = 0; it < 4; ++it) {
            const int idx = tid + 256 * it;
            const int b   = idx >> 4;
            const int kq  = (idx & 15) * 4;
            *(float4*)&As[b * 68 + kq] = *(const float4*)(g_xc + (size_t)b * 1024 + k0 + kq);
        }
#pragma unroll
        for (int it = 0; it < 2; ++it) {
            const int idx = tid + 256 * it;
            const int gg  = idx >> 4;
            const int kq  = (idx & 15) * 4;
            *(float4*)&Ws[gg * 68 + kq] = *(const float4*)(wbase + (size_t)gg * 1024 + k0 + kq);
        }
        __syncthreads();
#pragma unroll
        for (int kk = 0; kk < 64; kk += 4) {
            float4 wv = *(const float4*)&Ws[tx * 68 + kk];
#pragma unroll
            for (int i = 0; i < 8; ++i) {
                float4 av = *(const float4*)&As[(ty * 8 + i) * 68 + kk];
                acc[i] = fmaf(av.x, wv.x, acc[i]);
                acc[i] = fmaf(av.y, wv.y, acc[i]);
                acc[i] = fmaf(av.z, wv.z, acc[i]);
                acc[i] = fmaf(av.w, wv.w, acc[i]);
            }
        }
    }
#pragma unroll
    for (int i = 0; i < 8; ++i)
        g_g1[((size_t)d * 64 + ty * 8 + i) * 2048 + gB + tx] = acc[i];
}

// ---------------- K4: persistent recurrence kernel ----------------
// per_step=1: gin = g_g0 indexed per time step (dir 1 reversed); else gin = g_g1
// constant. outp==nullptr -> write final h into g_xc, else into outp (d_out).
__global__ __launch_bounds__(256, 1) void k_recur(const float* __restrict__ w_hh,
                                                  int per_step,
                                                  const float* __restrict__ lnh_g,
                                                  const float* __restrict__ lnh_b,
                                                  const float* __restrict__ lno_g,
                                                  const float* __restrict__ lno_b,
                                                  float* outp) {
    __shared__ float As[64 * 68];
    __shared__ float Ws[32 * 68];
    __shared__ float sred[8];
    const int tid = threadIdx.x;
    const int j   = blockIdx.x;
    // phase-A identity (GEMM slice)
    const int dA = j & 1;
    const int gB = (j >> 1) * 32;
    const int tx = tid & 31, ty = tid >> 5;
    // phase-B identity (cell row)
    const int dB = j >> 6;
    const int bB = j & 63;

    const float* gin = per_step ? g_g0 : g_g1;
    float* op = outp ? outp : g_xc;
    const float* wbase = w_hh + ((size_t)(dA * 2048 + gB)) * 512;

    float c0 = 0.f, c1 = 0.f;
    int nbar = 0;

    for (int step = 0; step < SS; ++step) {
        // ---- phase A: pre[dA][b][gB..gB+32) = h[dA][b][:] . w_hh[dA][g][:]
        float acc[8] = {0.f, 0.f, 0.f, 0.f, 0.f, 0.f, 0.f, 0.f};
        for (int k0 = 0; k0 < 512; k0 += 64) {
            __syncthreads();
#pragma unroll
            for (int it = 0; it < 4; ++it) {
                const int idx = tid + 256 * it;
                const int b   = idx >> 4;
                const int kq  = (idx & 15) * 4;
                float4 v = __ldcg((const float4*)(g_h + ((size_t)dA * 64 + b) * 512 + k0 + kq));
                *(float4*)&As[b * 68 + kq] = v;
            }
#pragma unroll
            for (int it = 0; it < 2; ++it) {
                const int idx = tid + 256 * it;
                const int gg  = idx >> 4;
                const int kq  = (idx & 15) * 4;
                *(float4*)&Ws[gg * 68 + kq] = *(const float4*)(wbase + (size_t)gg * 512 + k0 + kq);
            }
            __syncthreads();
#pragma unroll
            for (int kk = 0; kk < 64; kk += 4) {
                float4 wv = *(const float4*)&Ws[tx * 68 + kk];
#pragma unroll
                for (int i = 0; i < 8; ++i) {
                    float4 av = *(const float4*)&As[(ty * 8 + i) * 68 + kk];
                    acc[i] = fmaf(av.x, wv.x, acc[i]);
                    acc[i] = fmaf(av.y, wv.y, acc[i]);
                    acc[i] = fmaf(av.z, wv.z, acc[i]);
                    acc[i] = fmaf(av.w, wv.w, acc[i]);
                }
            }
        }
#pragma unroll
        for (int i = 0; i < 8; ++i)
            __stcg(g_pre + ((size_t)dA * 64 + ty * 8 + i) * 2048 + gB + tx, acc[i]);

        gbar(&nbar);   // pre ready

        // ---- phase B: gates, cell, output-LN for row (dB, bB)
        float v[8];
        const float* prow = g_pre + ((size_t)dB * 64 + bB) * 2048;
#pragma unroll
        for (int r = 0; r < 8; ++r) v[r] = __ldcg(prow + tid + 256 * r);

        float s = 0.f;
#pragma unroll
        for (int r = 0; r < 8; ++r) s += v[r];
        const float mu = blk_sum(s, sred) * (1.f / 2048.f);
        float sq = 0.f;
#pragma unroll
        for (int r = 0; r < 8; ++r) { const float t = v[r] - mu; sq += t * t; }
        const float var = blk_sum(sq, sred) * (1.f / 2048.f);
        const float rs  = rsqrtf(var + EPSL);

        const int s_eff = per_step ? ((dB == 0) ? step : (SS - 1 - step)) : 0;
        const float* grow = per_step
            ? gin + (((size_t)dB * SS + s_eff) * 64 + bB) * 2048
            : gin + ((size_t)dB * 64 + bB) * 2048;

        float gate[8];
#pragma unroll
        for (int r = 0; r < 8; ++r) {
            const int idx = tid + 256 * r;
            gate[r] = grow[idx] + ((v[r] - mu) * rs * lnh_g[dB * 2048 + idx] + lnh_b[dB * 2048 + idx]);
        }
        const float i0 = sigf(gate[0]), i1 = sigf(gate[1]);
        const float f0 = sigf(gate[2]), f1 = sigf(gate[3]);
        const float o0 = sigf(gate[4]), o1 = sigf(gate[5]);
        const float q0 = tanhf(gate[6]), q1 = tanhf(gate[7]);
        c0 = f0 * c0 + i0 * q0;
        c1 = f1 * c1 + i1 * q1;

        // LN over c (512), two values per thread
        const float muc = blk_sum(c0 + c1, sred) * (1.f / 512.f);
        const float t0 = c0 - muc, t1 = c1 - muc;
        const float varc = blk_sum(t0 * t0 + t1 * t1, sred) * (1.f / 512.f);
        const float rc = rsqrtf(varc + EPSL);
        const float h0 = o0 * tanhf(t0 * rc * lno_g[dB * 512 + tid]       + lno_b[dB * 512 + tid]);
        const float h1 = o1 * tanhf(t1 * rc * lno_g[dB * 512 + tid + 256] + lno_b[dB * 512 + tid + 256]);

        __stcg(g_h + ((size_t)dB * 64 + bB) * 512 + tid,       h0);
        __stcg(g_h + ((size_t)dB * 64 + bB) * 512 + tid + 256, h1);

        if (step == SS - 1) {
            op[(size_t)bB * 1024 + dB * 512 + tid]       = h0;
            op[(size_t)bB * 1024 + dB * 512 + tid + 256] = h1;
        }

        gbar(&nbar);   // h ready for next step's GEMM
    }
}

// ---------------- host launcher ----------------
extern "C" void kernel_launch(void* const* d_in, const int* in_sizes, int n_in,
                              void* d_out, int out_size) {
    const float* x        = (const float*)d_in[0];
    // d_in[1] = text_length (unused by the reference forward)
    const float* w_ih0    = (const float*)d_in[2];
    const float* w_hh0    = (const float*)d_in[3];
    const float* ln_ih0_g = (const float*)d_in[4];
    const float* ln_ih0_b = (const float*)d_in[5];
    const float* ln_hh0_g = (const float*)d_in[6];
    const float* ln_hh0_b = (const float*)d_in[7];
    const float* ln_ho0_g = (const float*)d_in[8];
    const float* ln_ho0_b = (const float*)d_in[9];
    const float* w_ih1    = (const float*)d_in[10];
    const float* w_hh1    = (const float*)d_in[11];
    const float* ln_ih1_g = (const float*)d_in[12];
    const float* ln_ih1_b = (const float*)d_in[13];
    const float* ln_hh1_g = (const float*)d_in[14];
    const float* ln_hh1_b = (const float*)d_in[15];
    const float* ln_ho1_g = (const float*)d_in[16];
    const float* ln_ho1_b = (const float*)d_in[17];
    float* out = (float*)d_out;

    // ---- layer 0 ----
    k_init<<<256, 256>>>();
    k_gemm_ih0<<<dim3(16, 48), 256>>>(x, w_ih0);
    k_ln_rows<<<6144, 256>>>(0, ln_ih0_g, ln_ih0_b, 3072);
    k_recur<<<NBLK, 256>>>(w_hh0, 1, ln_hh0_g, ln_hh0_b, ln_ho0_g, ln_ho0_b, nullptr);

    // ---- layer 1 ----
    k_init<<<256, 256>>>();
    k_gemm_xc<<<NBLK, 256>>>(w_ih1);
    k_ln_rows<<<128, 256>>>(1, ln_ih1_g, ln_ih1_b, 64);
    k_recur<<<NBLK, 256>>>(w_hh1, 0, ln_hh1_g, ln_hh1_b, ln_ho1_g, ln_ho1_b, out);
}